// round 4
// baseline (speedup 1.0000x reference)
#include <cuda_runtime.h>

#define MAXN 50000
#define MAXE 1600000
#define H 64

// ---------------- device scratch (no allocation allowed) ----------------
__device__ float g_hA[MAXN * H];     // node embeddings ping
__device__ float g_hB[MAXN * H];     // node embeddings pong
__device__ float g_neigh[MAXN * H];  // neighbor-sum accumulator
__device__ int   g_cnt[MAXN];        // out-degree (segment counts over src)
__device__ float g_ec[H * 4];        // fused edge constants: per j {M1[0..2], c1}

// ---------------- zero scratch ----------------
__global__ void k_zero(int n64, int n) {
    int i = blockIdx.x * blockDim.x + threadIdx.x;
    if (i < n64) g_neigh[i] = 0.f;
    if (i < n)   g_cnt[i] = 0;
}

// ---------------- precompute fused edge constants ----------------
// a = relu(M1 @ ef + c1) where
//   M1 = Wa[:, :64] @ We            (64x3)
//   c1 = Wa[:, :64] @ be + Wa[:, 64:] @ vnf_mean + ba
__global__ void k_pre(const float* __restrict__ enc, const float* __restrict__ Wa,
                      const float* __restrict__ ba, const float* __restrict__ We,
                      const float* __restrict__ be) {
    __shared__ float vm[H];
    int j = threadIdx.x;  // 64 threads
    float s = 0.f;
    #pragma unroll
    for (int v = 0; v < 16; v++) s += enc[v * H + j];
    vm[j] = s * (1.f / 16.f);
    __syncthreads();
    const float* wr = Wa + j * 128;  // Wa row j, (H+DM)=128 wide
    float m0 = 0.f, m1 = 0.f, m2 = 0.f, c = ba[j];
    #pragma unroll 8
    for (int m = 0; m < H; m++) {
        float w = wr[m];
        m0 += w * We[m * 3 + 0];
        m1 += w * We[m * 3 + 1];
        m2 += w * We[m * 3 + 2];
        c  += w * be[m];
    }
    #pragma unroll 8
    for (int d = 0; d < H; d++) c += wr[H + d] * vm[d];
    ((float4*)g_ec)[j] = make_float4(m0, m1, m2, c);
}

// ---------------- node_fc: h = node_feats @ Wn.T + bn ----------------
__global__ void k_nodefc(const float* __restrict__ nf, const float* __restrict__ Wn,
                         const float* __restrict__ bn, int N_) {
    __shared__ float Ws[H * 3];
    __shared__ float bs[H];
    int t = threadIdx.x;
    if (t < H * 3) Ws[t] = Wn[t];
    if (t < H) bs[t] = bn[t];
    __syncthreads();
    int idx = blockIdx.x * blockDim.x + t;
    if (idx >= N_ * H) return;
    int n = idx >> 6, j = idx & 63;
    float f0 = nf[n * 3 + 0], f1 = nf[n * 3 + 1], f2 = nf[n * 3 + 2];
    g_hA[idx] = Ws[j * 3 + 0] * f0 + Ws[j * 3 + 1] * f1 + Ws[j * 3 + 2] * f2 + bs[j];
}

// ---------------- fused edge scorer + degree count ----------------
// score = b2 + w2 . relu(W1 @ relu(M1 @ ef + c1) + b1)
__global__ __launch_bounds__(128) void k_scorer(
    const float* __restrict__ ef, const int* __restrict__ src,
    const float* __restrict__ W1, const float* __restrict__ b1,
    const float* __restrict__ W2, const float* __restrict__ b2,
    float* __restrict__ out, int E_) {
    __shared__ float4 W1s[H * H / 4];  // 16 KB, row-major float4
    __shared__ float4 ECs[H];
    __shared__ float b1s[H], w2s[H];
    __shared__ float b2s;
    int t = threadIdx.x;
    for (int i = t; i < H * H / 4; i += blockDim.x) W1s[i] = ((const float4*)W1)[i];
    if (t < H) {
        ECs[t] = ((const float4*)g_ec)[t];
        b1s[t] = b1[t];
        w2s[t] = W2[t];
    }
    if (t == 0) b2s = b2[0];
    __syncthreads();

    int e = blockIdx.x * blockDim.x + t;
    if (e >= E_) return;

    // degree (segment count over src)
    atomicAdd(&g_cnt[src[e]], 1);

    float f0 = ef[e * 3 + 0], f1 = ef[e * 3 + 1], f2 = ef[e * 3 + 2];
    float a[H];
    #pragma unroll
    for (int j = 0; j < H; j++) {
        float4 m = ECs[j];
        a[j] = fmaxf(m.x * f0 + m.y * f1 + m.z * f2 + m.w, 0.f);
    }
    float score = b2s;
    #pragma unroll 4
    for (int i = 0; i < H; i++) {
        float acc = b1s[i];
        #pragma unroll
        for (int q = 0; q < H / 4; q++) {
            float4 w = W1s[i * (H / 4) + q];
            acc += w.x * a[4 * q + 0] + w.y * a[4 * q + 1]
                 + w.z * a[4 * q + 2] + w.w * a[4 * q + 3];
        }
        score += w2s[i] * fmaxf(acc, 0.f);
    }
    out[e] = score;
}

// ---------------- neighbor scatter: neigh[src] += h[dst] ----------------
// one thread per (edge, 4-float chunk); vector red cuts atomic instr count 4x
__global__ void k_scatter(const int* __restrict__ ei, int E_, int which) {
    const float* hin = which ? g_hB : g_hA;
    int idx = blockIdx.x * blockDim.x + threadIdx.x;
    if (idx >= E_ * 16) return;
    int e = idx >> 4, c = idx & 15;
    int s = ei[e];        // src row
    int d = ei[E_ + e];   // dst row
    float4 v = *(const float4*)(hin + ((size_t)d << 6) + (c << 2));
    float* p = g_neigh + ((size_t)s << 6) + (c << 2);
    asm volatile("red.global.add.v4.f32 [%0], {%1,%2,%3,%4};"
                 :: "l"(p), "f"(v.x), "f"(v.y), "f"(v.z), "f"(v.w)
                 : "memory");
}

// ---------------- SAGE combine: h = relu(Wself@h + bself + Wneigh@mean + bneigh) ----
// block = (64, 4): 4 nodes per block, thread tx = output feature.
// W matrices repacked in shared as W4[kg][j] (float4 over k) -> conflict-free LDS128.
__global__ void k_combine(const float* __restrict__ Wself, const float* __restrict__ bself,
                          const float* __restrict__ Wneigh, const float* __restrict__ bneigh,
                          float* hout, int which_in, int use_hout, int N_) {
    const float* hin = which_in ? g_hB : g_hA;
    __shared__ float4 WsA[16 * H];  // [kg][j]
    __shared__ float4 WnA[16 * H];
    __shared__ float4 hs4[4][16];
    __shared__ float4 ns4[4][16];
    int tx = threadIdx.x, ty = threadIdx.y;
    int t = ty * 64 + tx;
    const float4* gs = (const float4*)Wself;   // gs[j*16+kg] = W[j][4kg..4kg+3]
    const float4* gn = (const float4*)Wneigh;
    for (int i = t; i < H * 16; i += 256) {
        int j = i >> 4, kg = i & 15;
        WsA[kg * H + j] = gs[i];
        WnA[kg * H + j] = gn[i];
    }
    int n = blockIdx.x * 4 + ty;
    if (n < N_) {
        ((float*)hs4)[t] = hin[(size_t)n * H + tx];
        int c = g_cnt[n];
        float rd = (c > 0) ? 1.f / (float)c : 1.f;
        ((float*)ns4)[t] = g_neigh[(size_t)n * H + tx] * rd;
    }
    __syncthreads();
    if (n >= N_) return;
    float acc = bself[tx] + bneigh[tx];
    #pragma unroll
    for (int kg = 0; kg < 16; kg++) {
        float4 hv = hs4[ty][kg];
        float4 nv = ns4[ty][kg];
        float4 ws = WsA[kg * H + tx];
        float4 wn = WnA[kg * H + tx];
        acc += hv.x * ws.x + hv.y * ws.y + hv.z * ws.z + hv.w * ws.w
             + nv.x * wn.x + nv.y * wn.y + nv.z * wn.z + nv.w * wn.w;
    }
    float r = fmaxf(acc, 0.f);
    float* o = use_hout ? hout : g_hB;
    o[(size_t)n * H + tx] = r;
}

// ---------------- launch ----------------
extern "C" void kernel_launch(void* const* d_in, const int* in_sizes, int n_in,
                              void* d_out, int out_size) {
    const float* node_feats = (const float*)d_in[0];
    const float* edge_feats = (const float*)d_in[1];
    const float* enc        = (const float*)d_in[2];
    const int*   ei         = (const int*)d_in[3];
    const float* Wn     = (const float*)d_in[4];
    const float* bn     = (const float*)d_in[5];
    const float* We     = (const float*)d_in[6];
    const float* be     = (const float*)d_in[7];
    const float* Wself  = (const float*)d_in[8];   // (2,64,64)
    const float* bself  = (const float*)d_in[9];   // (2,64)
    const float* Wneigh = (const float*)d_in[10];
    const float* bneigh = (const float*)d_in[11];
    const float* Wa     = (const float*)d_in[12];
    const float* ba     = (const float*)d_in[13];
    const float* W1     = (const float*)d_in[14];
    const float* b1     = (const float*)d_in[15];
    const float* W2     = (const float*)d_in[16];
    const float* b2     = (const float*)d_in[17];

    int N_ = in_sizes[0] / 3;
    int E_ = in_sizes[1] / 3;
    float* out = (float*)d_out;
    float* h_out = out + E_;  // output = [scores (E), h (N*64)]

    int n64 = N_ * H;
    dim3 cdim(64, 4);

    // 1. zero degree + neighbor accumulator
    k_zero<<<(n64 + 255) / 256, 256>>>(n64, N_);
    // 2. fused edge constants
    k_pre<<<1, 64>>>(enc, Wa, ba, We, be);
    // 3. node_fc
    k_nodefc<<<(n64 + 255) / 256, 256>>>(node_feats, Wn, bn, N_);
    // 4. edge scorer (also counts degree) -> out[0:E]
    k_scorer<<<(E_ + 127) / 128, 128>>>(edge_feats, ei, W1, b1, W2, b2, out, E_);
    // 5. layer 0: scatter from hA, combine -> hB
    k_scatter<<<(E_ * 16 + 255) / 256, 256>>>(ei, E_, 0);
    k_combine<<<(N_ + 3) / 4, cdim>>>(Wself, bself, Wneigh, bneigh,
                                      nullptr, 0, 0, N_);
    // 6. re-zero neighbor accumulator
    k_zero<<<(n64 + 255) / 256, 256>>>(n64, 0);
    // 7. layer 1: scatter from hB, combine -> d_out h region
    k_scatter<<<(E_ * 16 + 255) / 256, 256>>>(ei, E_, 1);
    k_combine<<<(N_ + 3) / 4, cdim>>>(Wself + H * H, bself + H,
                                      Wneigh + H * H, bneigh + H,
                                      h_out, 1, 1, N_);
}

// round 5
// speedup vs baseline: 1.0013x; 1.0013x over previous
#include <cuda_runtime.h>

#define MAXN 50000
#define MAXE 1600000
#define H 64

// ---------------- device scratch (no allocation allowed) ----------------
__device__ float g_hA[MAXN * H];     // node embeddings ping
__device__ float g_hB[MAXN * H];     // node embeddings pong
__device__ float g_neigh[MAXN * H];  // neighbor-sum accumulator
__device__ int   g_cnt[MAXN];        // out-degree (segment counts over src)
__device__ float g_ec[H * 4];        // fused edge constants: per j {M1[0..2], c1}

// ---------------- zero scratch ----------------
__global__ void k_zero(int n64, int n) {
    int i = blockIdx.x * blockDim.x + threadIdx.x;
    if (i < n64) g_neigh[i] = 0.f;
    if (i < n)   g_cnt[i] = 0;
}

// ---------------- precompute fused edge constants ----------------
// a = relu(M1 @ ef + c1) where
//   M1 = Wa[:, :64] @ We            (64x3)
//   c1 = Wa[:, :64] @ be + Wa[:, 64:] @ vnf_mean + ba
__global__ void k_pre(const float* __restrict__ enc, const float* __restrict__ Wa,
                      const float* __restrict__ ba, const float* __restrict__ We,
                      const float* __restrict__ be) {
    __shared__ float vm[H];
    int j = threadIdx.x;  // 64 threads
    float s = 0.f;
    #pragma unroll
    for (int v = 0; v < 16; v++) s += enc[v * H + j];
    vm[j] = s * (1.f / 16.f);
    __syncthreads();
    const float* wr = Wa + j * 128;  // Wa row j, (H+DM)=128 wide
    float m0 = 0.f, m1 = 0.f, m2 = 0.f, c = ba[j];
    #pragma unroll 8
    for (int m = 0; m < H; m++) {
        float w = wr[m];
        m0 += w * We[m * 3 + 0];
        m1 += w * We[m * 3 + 1];
        m2 += w * We[m * 3 + 2];
        c  += w * be[m];
    }
    #pragma unroll 8
    for (int d = 0; d < H; d++) c += wr[H + d] * vm[d];
    ((float4*)g_ec)[j] = make_float4(m0, m1, m2, c);
}

// ---------------- node_fc: h = node_feats @ Wn.T + bn ----------------
__global__ void k_nodefc(const float* __restrict__ nf, const float* __restrict__ Wn,
                         const float* __restrict__ bn, int N_) {
    __shared__ float Ws[H * 3];
    __shared__ float bs[H];
    int t = threadIdx.x;
    if (t < H * 3) Ws[t] = Wn[t];
    if (t < H) bs[t] = bn[t];
    __syncthreads();
    int idx = blockIdx.x * blockDim.x + t;
    if (idx >= N_ * H) return;
    int n = idx >> 6, j = idx & 63;
    float f0 = nf[n * 3 + 0], f1 = nf[n * 3 + 1], f2 = nf[n * 3 + 2];
    g_hA[idx] = Ws[j * 3 + 0] * f0 + Ws[j * 3 + 1] * f1 + Ws[j * 3 + 2] * f2 + bs[j];
}

// ---------------- fused edge scorer + degree count ----------------
// score = b2 + w2 . relu(W1 @ relu(M1 @ ef + c1) + b1)
__global__ __launch_bounds__(128) void k_scorer(
    const float* __restrict__ ef, const int* __restrict__ src,
    const float* __restrict__ W1, const float* __restrict__ b1,
    const float* __restrict__ W2, const float* __restrict__ b2,
    float* __restrict__ out, int E_) {
    __shared__ float4 W1s[H * H / 4];  // 16 KB, row-major float4
    __shared__ float4 ECs[H];
    __shared__ float b1s[H], w2s[H];
    __shared__ float b2s;
    int t = threadIdx.x;
    for (int i = t; i < H * H / 4; i += blockDim.x) W1s[i] = ((const float4*)W1)[i];
    if (t < H) {
        ECs[t] = ((const float4*)g_ec)[t];
        b1s[t] = b1[t];
        w2s[t] = W2[t];
    }
    if (t == 0) b2s = b2[0];
    __syncthreads();

    int e = blockIdx.x * blockDim.x + t;
    if (e >= E_) return;

    // degree (segment count over src)
    atomicAdd(&g_cnt[src[e]], 1);

    float f0 = ef[e * 3 + 0], f1 = ef[e * 3 + 1], f2 = ef[e * 3 + 2];
    float a[H];
    #pragma unroll
    for (int j = 0; j < H; j++) {
        float4 m = ECs[j];
        a[j] = fmaxf(m.x * f0 + m.y * f1 + m.z * f2 + m.w, 0.f);
    }
    float score = b2s;
    #pragma unroll 4
    for (int i = 0; i < H; i++) {
        float acc = b1s[i];
        #pragma unroll
        for (int q = 0; q < H / 4; q++) {
            float4 w = W1s[i * (H / 4) + q];
            acc += w.x * a[4 * q + 0] + w.y * a[4 * q + 1]
                 + w.z * a[4 * q + 2] + w.w * a[4 * q + 3];
        }
        score += w2s[i] * fmaxf(acc, 0.f);
    }
    out[e] = score;
}

// ---------------- neighbor scatter: neigh[src] += h[dst] ----------------
// one thread per (edge, 4-float chunk); vector red cuts atomic instr count 4x
__global__ void k_scatter(const int* __restrict__ ei, int E_, int which) {
    const float* hin = which ? g_hB : g_hA;
    int idx = blockIdx.x * blockDim.x + threadIdx.x;
    if (idx >= E_ * 16) return;
    int e = idx >> 4, c = idx & 15;
    int s = ei[e];        // src row
    int d = ei[E_ + e];   // dst row
    float4 v = *(const float4*)(hin + ((size_t)d << 6) + (c << 2));
    float* p = g_neigh + ((size_t)s << 6) + (c << 2);
    asm volatile("red.global.add.v4.f32 [%0], {%1,%2,%3,%4};"
                 :: "l"(p), "f"(v.x), "f"(v.y), "f"(v.z), "f"(v.w)
                 : "memory");
}

// ---------------- SAGE combine: h = relu(Wself@h + bself + Wneigh@mean + bneigh) ----
// block = (64, 4): 4 nodes per block, thread tx = output feature.
// W matrices repacked in shared as W4[kg][j] (float4 over k) -> conflict-free LDS128.
__global__ void k_combine(const float* __restrict__ Wself, const float* __restrict__ bself,
                          const float* __restrict__ Wneigh, const float* __restrict__ bneigh,
                          float* hout, int which_in, int use_hout, int N_) {
    const float* hin = which_in ? g_hB : g_hA;
    __shared__ float4 WsA[16 * H];  // [kg][j]
    __shared__ float4 WnA[16 * H];
    __shared__ float4 hs4[4][16];
    __shared__ float4 ns4[4][16];
    int tx = threadIdx.x, ty = threadIdx.y;
    int t = ty * 64 + tx;
    const float4* gs = (const float4*)Wself;   // gs[j*16+kg] = W[j][4kg..4kg+3]
    const float4* gn = (const float4*)Wneigh;
    for (int i = t; i < H * 16; i += 256) {
        int j = i >> 4, kg = i & 15;
        WsA[kg * H + j] = gs[i];
        WnA[kg * H + j] = gn[i];
    }
    int n = blockIdx.x * 4 + ty;
    if (n < N_) {
        ((float*)hs4)[t] = hin[(size_t)n * H + tx];
        int c = g_cnt[n];
        float rd = (c > 0) ? 1.f / (float)c : 1.f;
        ((float*)ns4)[t] = g_neigh[(size_t)n * H + tx] * rd;
    }
    __syncthreads();
    if (n >= N_) return;
    float acc = bself[tx] + bneigh[tx];
    #pragma unroll
    for (int kg = 0; kg < 16; kg++) {
        float4 hv = hs4[ty][kg];
        float4 nv = ns4[ty][kg];
        float4 ws = WsA[kg * H + tx];
        float4 wn = WnA[kg * H + tx];
        acc += hv.x * ws.x + hv.y * ws.y + hv.z * ws.z + hv.w * ws.w
             + nv.x * wn.x + nv.y * wn.y + nv.z * wn.z + nv.w * wn.w;
    }
    float r = fmaxf(acc, 0.f);
    float* o = use_hout ? hout : g_hB;
    o[(size_t)n * H + tx] = r;
}

// ---------------- launch ----------------
extern "C" void kernel_launch(void* const* d_in, const int* in_sizes, int n_in,
                              void* d_out, int out_size) {
    const float* node_feats = (const float*)d_in[0];
    const float* edge_feats = (const float*)d_in[1];
    const float* enc        = (const float*)d_in[2];
    const int*   ei         = (const int*)d_in[3];
    const float* Wn     = (const float*)d_in[4];
    const float* bn     = (const float*)d_in[5];
    const float* We     = (const float*)d_in[6];
    const float* be     = (const float*)d_in[7];
    const float* Wself  = (const float*)d_in[8];   // (2,64,64)
    const float* bself  = (const float*)d_in[9];   // (2,64)
    const float* Wneigh = (const float*)d_in[10];
    const float* bneigh = (const float*)d_in[11];
    const float* Wa     = (const float*)d_in[12];
    const float* ba     = (const float*)d_in[13];
    const float* W1     = (const float*)d_in[14];
    const float* b1     = (const float*)d_in[15];
    const float* W2     = (const float*)d_in[16];
    const float* b2     = (const float*)d_in[17];

    int N_ = in_sizes[0] / 3;
    int E_ = in_sizes[1] / 3;
    float* out = (float*)d_out;
    float* h_out = out + E_;  // output = [scores (E), h (N*64)]

    int n64 = N_ * H;
    dim3 cdim(64, 4);

    // 1. zero degree + neighbor accumulator
    k_zero<<<(n64 + 255) / 256, 256>>>(n64, N_);
    // 2. fused edge constants
    k_pre<<<1, 64>>>(enc, Wa, ba, We, be);
    // 3. node_fc
    k_nodefc<<<(n64 + 255) / 256, 256>>>(node_feats, Wn, bn, N_);
    // 4. edge scorer (also counts degree) -> out[0:E]
    k_scorer<<<(E_ + 127) / 128, 128>>>(edge_feats, ei, W1, b1, W2, b2, out, E_);
    // 5. layer 0: scatter from hA, combine -> hB
    k_scatter<<<(E_ * 16 + 255) / 256, 256>>>(ei, E_, 0);
    k_combine<<<(N_ + 3) / 4, cdim>>>(Wself, bself, Wneigh, bneigh,
                                      nullptr, 0, 0, N_);
    // 6. re-zero neighbor accumulator
    k_zero<<<(n64 + 255) / 256, 256>>>(n64, 0);
    // 7. layer 1: scatter from hB, combine -> d_out h region
    k_scatter<<<(E_ * 16 + 255) / 256, 256>>>(ei, E_, 1);
    k_combine<<<(N_ + 3) / 4, cdim>>>(Wself + H * H, bself + H,
                                      Wneigh + H * H, bneigh + H,
                                      h_out, 1, 1, N_);
}